// round 5
// baseline (speedup 1.0000x reference)
#include <cuda_runtime.h>
#include <cstdint>
#include <cstdio>

// Problem constants
#define TT   256
#define NN   1024
#define HH   256
#define OUTW 278   // 4 + 256 + 16 + 2

#define SMEM128 69632   // 2 bufs * (128+128) rows * 34 floats * 4B
#define SMEM64  34816   // 2 bufs * (64+64)  rows * 34 floats * 4B

// ---------------- scratch (device globals; no allocations allowed) ----------------
__device__ float S_MFLAT[16384 * 256];          // embed[lines] rows n*L+l
__device__ float S_GF[16384 * 768];             // forward  gi per distinct (n,l)
__device__ float S_GB[16384 * 768];             // backward gi per distinct (n,l)
__device__ float S_GH[16384 * 768];             // encoder gh scratch
__device__ float S_GHM[1024 * 768];             // main-loop gh scratch
__device__ float S_E0[16384 * 256];             // encoder ping-pong fwd
__device__ float S_E1[16384 * 256];
__device__ float S_E2[16384 * 256];             // encoder ping-pong bwd
__device__ float S_E3[16384 * 256];
__device__ float S_HCAT[16384 * 512];           // concat(hf, hb) rows l*N+n
__device__ float S_RP[16384 * 256];             // f_w0[:,C:] @ Hmem
__device__ float S_B1[262144 * 256];            // Acond, later reused as X3
__device__ float S_X1[262144 * 256];
__device__ float S_X2[262144 * 256];
__device__ float S_GI[(size_t)262144 * 768];    // main-loop gi for all t
__device__ float S_H0[1024 * 256];              // main-loop h ping-pong
__device__ float S_H1[1024 * 256];

__device__ __forceinline__ float sigm(float x) { return 1.0f / (1.0f + expf(-x)); }

__device__ __forceinline__ void spl(float x, unsigned& hi, unsigned& lo) {
    unsigned b = __float_as_uint(x);
    hi = b & 0xffffe000u;                 // bits the tf32 HW path keeps
    lo = __float_as_uint(x - __uint_as_float(hi));
}

__device__ __forceinline__ void mma8(float* c, const unsigned* a, const unsigned* b) {
    asm volatile(
        "mma.sync.aligned.m16n8k8.row.col.f32.tf32.tf32.f32 "
        "{%0,%1,%2,%3}, {%4,%5,%6,%7}, {%8,%9}, {%0,%1,%2,%3};"
        : "+f"(c[0]), "+f"(c[1]), "+f"(c[2]), "+f"(c[3])
        : "r"(a[0]), "r"(a[1]), "r"(a[2]), "r"(a[3]), "r"(b[0]), "r"(b[1]));
}

// ---------------- tf32 tensor-core GEMM v3: C = op(A @ W^T + bias) ----------------
// A: [M,K] row-major (lda); W rows at W[row*ldw + wcol0 + k]; C: [M,Nc] (ldc).
// k-permuted smem layout: pk = (k&3)*8 + (k>>2), row stride 34 floats.
// Thread's fragment k-values (k, k+4) are adjacent -> LDS.64 per fragment pair.
// 8 warps (4M x 2N). M%BMT==0, Nc%BNT==0, K%32==0.
template<int SPLIT3, int BMT, int BNT>
__global__ __launch_bounds__(256) void mma_v3(
    const float* __restrict__ A, int lda,
    const float* __restrict__ W, int ldw, int wcol0,
    const float* __restrict__ bias,
    float* __restrict__ C, int ldc, int K, int relu)
{
    constexpr int WTM = BMT / 4, WTN = BNT / 2;
    constexpr int MF  = WTM / 16, NF = WTN / 8;
    constexpr int AJ  = BMT / 32, BJ = BNT / 32;
    constexpr int SA  = BMT * 34, SB = BNT * 34;
    extern __shared__ float sm[];
    float* AsBase = sm;              // [2][BMT][34]
    float* BsBase = sm + 2 * SA;     // [2][BNT][34]

    const int tid  = threadIdx.x;
    const int lane = tid & 31, warp = tid >> 5;
    const int bm = blockIdx.x * BMT, bn = blockIdx.y * BNT;
    const int wm = (warp & 3) * WTM, wn = (warp >> 2) * WTN;
    const int lr = lane >> 2, lk = lane & 3;
    const int mld = tid >> 3, g = tid & 7;      // loader: row tid>>3, k-quad g*4

    float acc[MF][NF][4] = {};
    const int KT = K / 32;

    float4 av[AJ], wv[BJ];

    // prologue: load + store tile 0
    {
        const float* Ab = A + (size_t)(bm + mld) * lda + g * 4;
        const float* Wb = W + (size_t)(bn + mld) * ldw + wcol0 + g * 4;
#pragma unroll
        for (int j = 0; j < AJ; j++) av[j] = *(const float4*)(Ab + (size_t)(32 * j) * lda);
#pragma unroll
        for (int j = 0; j < BJ; j++) wv[j] = *(const float4*)(Wb + (size_t)(32 * j) * ldw);
#pragma unroll
        for (int j = 0; j < AJ; j++) {
            float* p = AsBase + (mld + 32 * j) * 34 + g;
            p[0] = av[j].x; p[8] = av[j].y; p[16] = av[j].z; p[24] = av[j].w;
        }
#pragma unroll
        for (int j = 0; j < BJ; j++) {
            float* p = BsBase + (mld + 32 * j) * 34 + g;
            p[0] = wv[j].x; p[8] = wv[j].y; p[16] = wv[j].z; p[24] = wv[j].w;
        }
    }

    for (int kt = 0; kt < KT; kt++) {
        __syncthreads();
        const int buf = kt & 1;
        if (kt + 1 < KT) {
            int k0 = (kt + 1) * 32;
            const float* Ab = A + (size_t)(bm + mld) * lda + k0 + g * 4;
            const float* Wb = W + (size_t)(bn + mld) * ldw + wcol0 + k0 + g * 4;
#pragma unroll
            for (int j = 0; j < AJ; j++) av[j] = *(const float4*)(Ab + (size_t)(32 * j) * lda);
#pragma unroll
            for (int j = 0; j < BJ; j++) wv[j] = *(const float4*)(Wb + (size_t)(32 * j) * ldw);
        }

        const float* Ab = AsBase + buf * SA;
        const float* Bb = BsBase + buf * SB;
#pragma unroll
        for (int s = 0; s < 4; s++) {
            unsigned ah[MF][4], al[MF][4], bh[NF][2], bl[NF][2];
#pragma unroll
            for (int mf = 0; mf < MF; mf++) {
                int r0 = wm + mf * 16 + lr;
                float2 x0 = *(const float2*)(Ab + r0 * 34 + lk * 8 + 2 * s);
                float2 x1 = *(const float2*)(Ab + (r0 + 8) * 34 + lk * 8 + 2 * s);
                if (SPLIT3) {
                    spl(x0.x, ah[mf][0], al[mf][0]); spl(x1.x, ah[mf][1], al[mf][1]);
                    spl(x0.y, ah[mf][2], al[mf][2]); spl(x1.y, ah[mf][3], al[mf][3]);
                } else {
                    ah[mf][0] = __float_as_uint(x0.x); ah[mf][1] = __float_as_uint(x1.x);
                    ah[mf][2] = __float_as_uint(x0.y); ah[mf][3] = __float_as_uint(x1.y);
                }
            }
#pragma unroll
            for (int nf = 0; nf < NF; nf++) {
                int c0 = wn + nf * 8 + lr;
                float2 y = *(const float2*)(Bb + c0 * 34 + lk * 8 + 2 * s);
                if (SPLIT3) {
                    spl(y.x, bh[nf][0], bl[nf][0]); spl(y.y, bh[nf][1], bl[nf][1]);
                } else {
                    bh[nf][0] = __float_as_uint(y.x); bh[nf][1] = __float_as_uint(y.y);
                }
            }
#pragma unroll
            for (int mf = 0; mf < MF; mf++)
#pragma unroll
                for (int nf = 0; nf < NF; nf++) {
                    mma8(acc[mf][nf], ah[mf], bh[nf]);
                    if (SPLIT3) {
                        mma8(acc[mf][nf], ah[mf], bl[nf]);
                        mma8(acc[mf][nf], al[mf], bh[nf]);
                    }
                }
        }

        if (kt + 1 < KT) {
            float* Ad = AsBase + (buf ^ 1) * SA;
            float* Bd = BsBase + (buf ^ 1) * SB;
#pragma unroll
            for (int j = 0; j < AJ; j++) {
                float* p = Ad + (mld + 32 * j) * 34 + g;
                p[0] = av[j].x; p[8] = av[j].y; p[16] = av[j].z; p[24] = av[j].w;
            }
#pragma unroll
            for (int j = 0; j < BJ; j++) {
                float* p = Bd + (mld + 32 * j) * 34 + g;
                p[0] = wv[j].x; p[8] = wv[j].y; p[16] = wv[j].z; p[24] = wv[j].w;
            }
        }
    }

#pragma unroll
    for (int mf = 0; mf < MF; mf++) {
#pragma unroll
        for (int nf = 0; nf < NF; nf++) {
            int col = bn + wn + nf * 8 + lk * 2;
            float b0v = 0.f, b1v = 0.f;
            if (bias) { b0v = bias[col]; b1v = bias[col + 1]; }
            int r0 = bm + wm + mf * 16 + lr;
            float v0 = acc[mf][nf][0] + b0v, v1 = acc[mf][nf][1] + b1v;
            float v2 = acc[mf][nf][2] + b0v, v3 = acc[mf][nf][3] + b1v;
            if (relu) {
                v0 = fmaxf(v0, 0.f); v1 = fmaxf(v1, 0.f);
                v2 = fmaxf(v2, 0.f); v3 = fmaxf(v3, 0.f);
            }
            float2 p0; p0.x = v0; p0.y = v1;
            float2 p1; p1.x = v2; p1.y = v3;
            *reinterpret_cast<float2*>(&C[(size_t)r0 * ldc + col]) = p0;
            *reinterpret_cast<float2*>(&C[(size_t)(r0 + 8) * ldc + col]) = p1;
        }
    }
}

// ---------------- elementwise GRU gate kernels (float4) ----------------
// encoder: b = roll*1024+n; gi row = n*16 + ((roll + loff) & 15)
__global__ void enc_gate_kernel(const float* __restrict__ Hin,
                                const float* __restrict__ GH,
                                const float* __restrict__ GI,
                                const float* __restrict__ bhh,
                                float* __restrict__ Hout,
                                int loff, int hzero)
{
    int b = blockIdx.x * 4 + (threadIdx.x >> 6);
    int j = (threadIdx.x & 63) * 4;
    int n = b & 1023, roll = b >> 10;
    int l = (roll + loff) & 15;
    const float* gi = GI + ((size_t)n * 16 + l) * 768;
    float4 gr = *(const float4*)(gi + j);
    float4 gz = *(const float4*)(gi + 256 + j);
    float4 gn = *(const float4*)(gi + 512 + j);
    float4 hr = *(const float4*)(bhh + j);
    float4 hz = *(const float4*)(bhh + 256 + j);
    float4 hn = *(const float4*)(bhh + 512 + j);
    float4 h = make_float4(0.f, 0.f, 0.f, 0.f);
    if (!hzero) {
        const float* gh = GH + (size_t)b * 768;
        float4 t;
        t = *(const float4*)(gh + j);       hr.x += t.x; hr.y += t.y; hr.z += t.z; hr.w += t.w;
        t = *(const float4*)(gh + 256 + j); hz.x += t.x; hz.y += t.y; hz.z += t.z; hz.w += t.w;
        t = *(const float4*)(gh + 512 + j); hn.x += t.x; hn.y += t.y; hn.z += t.z; hn.w += t.w;
        h = *(const float4*)(Hin + (size_t)b * 256 + j);
    }
    float4 o;
    {
        float r = sigm(gr.x + hr.x), z = sigm(gz.x + hz.x);
        o.x = (1.f - z) * tanhf(gn.x + r * hn.x) + z * h.x;
    }
    {
        float r = sigm(gr.y + hr.y), z = sigm(gz.y + hz.y);
        o.y = (1.f - z) * tanhf(gn.y + r * hn.y) + z * h.y;
    }
    {
        float r = sigm(gr.z + hr.z), z = sigm(gz.z + hz.z);
        o.z = (1.f - z) * tanhf(gn.z + r * hn.z) + z * h.z;
    }
    {
        float r = sigm(gr.w + hr.w), z = sigm(gz.w + hz.w);
        o.w = (1.f - z) * tanhf(gn.w + r * hn.w) + z * h.w;
    }
    *(float4*)(Hout + (size_t)b * 256 + j) = o;
}

// main loop: also writes h into out[t,n,4+j]
__global__ void main_gate_kernel(const float* __restrict__ Hin,
                                 const float* __restrict__ GH,
                                 const float* __restrict__ GI,
                                 const float* __restrict__ bhh,
                                 float* __restrict__ Hout,
                                 float* __restrict__ out, int t)
{
    int b = blockIdx.x * 4 + (threadIdx.x >> 6);
    int j = (threadIdx.x & 63) * 4;
    const float* gi = GI + ((size_t)t * 1024 + b) * 768;
    const float* gh = GH + (size_t)b * 768;
    float4 gr = *(const float4*)(gi + j);
    float4 gz = *(const float4*)(gi + 256 + j);
    float4 gn = *(const float4*)(gi + 512 + j);
    float4 qr = *(const float4*)(gh + j);
    float4 qz = *(const float4*)(gh + 256 + j);
    float4 qn = *(const float4*)(gh + 512 + j);
    float4 br = *(const float4*)(bhh + j);
    float4 bz = *(const float4*)(bhh + 256 + j);
    float4 bn = *(const float4*)(bhh + 512 + j);
    float4 h = *(const float4*)(Hin + (size_t)b * 256 + j);
    float4 o;
    {
        float r = sigm(gr.x + qr.x + br.x), z = sigm(gz.x + qz.x + bz.x);
        o.x = (1.f - z) * tanhf(gn.x + r * (qn.x + bn.x)) + z * h.x;
    }
    {
        float r = sigm(gr.y + qr.y + br.y), z = sigm(gz.y + qz.y + bz.y);
        o.y = (1.f - z) * tanhf(gn.y + r * (qn.y + bn.y)) + z * h.y;
    }
    {
        float r = sigm(gr.z + qr.z + br.z), z = sigm(gz.z + qz.z + bz.z);
        o.z = (1.f - z) * tanhf(gn.z + r * (qn.z + bn.z)) + z * h.z;
    }
    {
        float r = sigm(gr.w + qr.w + br.w), z = sigm(gz.w + qz.w + bz.w);
        o.w = (1.f - z) * tanhf(gn.w + r * (qn.w + bn.w)) + z * h.w;
    }
    *(float4*)(Hout + (size_t)b * 256 + j) = o;
    float* orow = out + ((size_t)t * 1024 + b) * OUTW + 4 + j;
    float2 w0; w0.x = o.x; w0.y = o.y;
    float2 w1; w1.x = o.z; w1.y = o.w;
    *(float2*)orow = w0;
    *(float2*)(orow + 2) = w1;
}

// ---------------- misc small kernels (float4) ----------------
__global__ void gather_kernel(const int* __restrict__ lines,
                              const float* __restrict__ embed)
{
    int gid = blockIdx.x * 256 + threadIdx.x;
    int e = gid * 4;
    int row = e >> 8, j = e & 255;              // row = n*L+l
    int line = lines[row];
    *(float4*)(S_MFLAT + (size_t)row * 256 + j) =
        *(const float4*)(embed + (size_t)line * 256 + j);
}

__global__ void hcat_kernel()
{
    int gid = blockIdx.x * 256 + threadIdx.x;
    int e = gid * 4;
    int row = e >> 9, c = e & 511;              // row = l*N+n
    float4 v;
    if (c < 256) v = *(const float4*)(S_E0 + (size_t)row * 256 + c);
    else         v = *(const float4*)(S_E2 + (size_t)row * 256 + c - 256);
    *(float4*)(S_HCAT + (size_t)row * 512 + c) = v;
}

__global__ void x1_kernel(const int* __restrict__ active,
                          const float* __restrict__ b0)
{
    size_t gid = (size_t)blockIdx.x * 256 + threadIdx.x;
    size_t e = gid * 4;
    size_t row = e >> 8;                        // t*N + n
    int j = (int)(e & 255);
    int n = (int)(row & 1023);
    int w = active[row];
    float4 a = *(const float4*)(S_B1 + row * 256 + j);
    float4 r = *(const float4*)(S_RP + ((size_t)w * 1024 + n) * 256 + j);
    float4 b = *(const float4*)(b0 + j);
    float4 o;
    o.x = fmaxf(a.x + r.x + b.x, 0.f);
    o.y = fmaxf(a.y + r.y + b.y, 0.f);
    o.z = fmaxf(a.z + r.z + b.z, 0.f);
    o.w = fmaxf(a.w + r.w + b.w, 0.f);
    *(float4*)(S_X1 + row * 256 + j) = o;
}

// actor/critic/softmax + packing of a/p/w/pp, reading h back from out
__global__ __launch_bounds__(256) void head_kernel(
    float* __restrict__ out,
    const float* __restrict__ w_actor, const float* __restrict__ b_actor,
    const float* __restrict__ w_critic, const float* __restrict__ b_critic,
    const int* __restrict__ actions, const int* __restrict__ active,
    const float* __restrict__ p0, const float* __restrict__ pp0)
{
    __shared__ float wa[16][257];
    __shared__ float wc[256];
    int tid = threadIdx.x;
    for (int idx = tid; idx < 16 * 256; idx += 256)
        wa[idx >> 8][idx & 255] = w_actor[idx];
    wc[tid] = w_critic[tid];
    __syncthreads();

    int warp = tid >> 5, lane = tid & 31;
#pragma unroll 1
    for (int rr = 0; rr < 4; rr++) {
        size_t row = (size_t)blockIdx.x * 32 + warp * 4 + rr;   // 0..262143
        float* orow = out + row * OUTW;
        const float* hrow = orow + 4;
        const float* wrow = (lane < 16) ? wa[lane] : wc;
        float acc = 0.0f;
#pragma unroll 8
        for (int j = 0; j < 256; j++) acc += hrow[j] * wrow[j];
        if (lane < 16) acc += b_actor[lane];
        else if (lane == 16) acc += b_critic[0];

        // softmax among lanes 0..15
        float lg = (lane < 16) ? acc : -1e30f;
        float m = lg;
#pragma unroll
        for (int o = 8; o > 0; o >>= 1)
            m = fmaxf(m, __shfl_xor_sync(0xffffffffu, m, o, 16));
        float e = expf(lg - m);
        float s = e;
#pragma unroll
        for (int o = 8; o > 0; o >>= 1)
            s += __shfl_xor_sync(0xffffffffu, s, o, 16);
        float p = e / s;

        int n = (int)(row & 1023);
        if (lane < 16)       orow[260 + lane] = p;
        else if (lane == 16) orow[3]   = acc;
        else if (lane == 17) orow[0]   = (float)actions[row];
        else if (lane == 18) orow[1]   = p0[n];
        else if (lane == 19) orow[2]   = (float)active[row];
        else if (lane == 20) orow[276] = pp0[2 * n];
        else if (lane == 21) orow[277] = pp0[2 * n + 1];
    }
}

// ---------------- launcher ----------------
extern "C" void kernel_launch(void* const* d_in, const int* in_sizes, int n_in,
                              void* d_out, int out_size)
{
    const float* condition = (const float*)d_in[0];
    const int*   active    = (const int*)d_in[1];
    const int*   lines     = (const int*)d_in[2];
    const int*   actions   = (const int*)d_in[3];
    const float* h0        = (const float*)d_in[4];
    const float* p0        = (const float*)d_in[5];
    const float* pp0       = (const float*)d_in[6];
    const float* embed     = (const float*)d_in[7];
    const float* wih_f     = (const float*)d_in[8];
    const float* whh_f     = (const float*)d_in[9];
    const float* bih_f     = (const float*)d_in[10];
    const float* bhh_f     = (const float*)d_in[11];
    const float* wih_b     = (const float*)d_in[12];
    const float* whh_b     = (const float*)d_in[13];
    const float* bih_b     = (const float*)d_in[14];
    const float* bhh_b     = (const float*)d_in[15];
    const float* f_w0      = (const float*)d_in[16];
    const float* f_b0      = (const float*)d_in[17];
    const float* f_w1      = (const float*)d_in[18];
    const float* f_b1      = (const float*)d_in[19];
    const float* f_w2      = (const float*)d_in[20];
    const float* f_b2      = (const float*)d_in[21];
    const float* c_wih     = (const float*)d_in[22];
    const float* c_whh     = (const float*)d_in[23];
    const float* c_bih     = (const float*)d_in[24];
    const float* c_bhh     = (const float*)d_in[25];
    const float* w_critic  = (const float*)d_in[26];
    const float* b_critic  = (const float*)d_in[27];
    const float* w_actor   = (const float*)d_in[28];
    const float* b_actor   = (const float*)d_in[29];
    float* out = (float*)d_out;

    float *mflat, *gf, *gb, *gh, *ghm, *e0, *e1, *e2, *e3, *hcat, *rp, *b1, *x1, *x2, *gi, *hh0, *hh1;
    cudaGetSymbolAddress((void**)&mflat, S_MFLAT);
    cudaGetSymbolAddress((void**)&gf,    S_GF);
    cudaGetSymbolAddress((void**)&gb,    S_GB);
    cudaGetSymbolAddress((void**)&gh,    S_GH);
    cudaGetSymbolAddress((void**)&ghm,   S_GHM);
    cudaGetSymbolAddress((void**)&e0,    S_E0);
    cudaGetSymbolAddress((void**)&e1,    S_E1);
    cudaGetSymbolAddress((void**)&e2,    S_E2);
    cudaGetSymbolAddress((void**)&e3,    S_E3);
    cudaGetSymbolAddress((void**)&hcat,  S_HCAT);
    cudaGetSymbolAddress((void**)&rp,    S_RP);
    cudaGetSymbolAddress((void**)&b1,    S_B1);
    cudaGetSymbolAddress((void**)&x1,    S_X1);
    cudaGetSymbolAddress((void**)&x2,    S_X2);
    cudaGetSymbolAddress((void**)&gi,    S_GI);
    cudaGetSymbolAddress((void**)&hh0,   S_H0);
    cudaGetSymbolAddress((void**)&hh1,   S_H1);

    cudaFuncSetAttribute(mma_v3<0, 128, 128>, cudaFuncAttributeMaxDynamicSharedMemorySize, SMEM128);
    cudaFuncSetAttribute(mma_v3<1, 64, 64>,   cudaFuncAttributeMaxDynamicSharedMemorySize, SMEM64);

    // ---- task encoder ----
    gather_kernel<<<4096, 256>>>(lines, embed);

    // gi precompute over the 16384 distinct (n,l) rows (includes bih)
    mma_v3<0, 128, 128><<<dim3(128, 6), 256, SMEM128>>>(mflat, 256, wih_f, 256, 0, bih_f, gf, 768, 256, 0);
    mma_v3<0, 128, 128><<<dim3(128, 6), 256, SMEM128>>>(mflat, 256, wih_b, 256, 0, bih_b, gb, 768, 256, 0);

    // forward scan: gh GEMM (tf32) + elementwise gates
    for (int t = 0; t < 16; t++) {
        const float* src = (t & 1) ? e1 : e0;
        float* dst = (t & 1) ? e0 : e1;        // t=15 (odd) -> e0 final
        if (t > 0)
            mma_v3<0, 128, 128><<<dim3(128, 6), 256, SMEM128>>>(src, 256, whh_f, 256, 0, nullptr,
                                                                gh, 768, 256, 0);
        enc_gate_kernel<<<4096, 256>>>(src, gh, gf, bhh_f, dst, t, t == 0);
    }
    // backward scan
    for (int s = 0; s < 16; s++) {
        const float* src = (s & 1) ? e3 : e2;
        float* dst = (s & 1) ? e2 : e3;        // s=15 -> e2 final
        if (s > 0)
            mma_v3<0, 128, 128><<<dim3(128, 6), 256, SMEM128>>>(src, 256, whh_b, 256, 0, nullptr,
                                                                gh, 768, 256, 0);
        enc_gate_kernel<<<4096, 256>>>(src, gh, gb, bhh_b, dst, 15 - s, s == 0);
    }
    hcat_kernel<<<8192, 256>>>();

    // ---- main-loop parallel precompute ----
    // Rp[l*N+n] = Hmem @ f_w0[:, C:].T   (K=512)
    mma_v3<0, 128, 128><<<dim3(128, 2), 256, SMEM128>>>(hcat, 512, f_w0, 576, 64, nullptr, rp, 256, 512, 0);
    // Acond[t*N+n] = cond @ f_w0[:, :C].T   (K=64, into b1)
    mma_v3<0, 128, 128><<<dim3(2048, 2), 256, SMEM128>>>(condition, 64, f_w0, 576, 0, nullptr, b1, 256, 64, 0);
    // x1 = relu(Acond + gather(Rp) + b0)
    x1_kernel<<<65536, 256>>>(active, f_b0);
    // x2 = relu(x1 @ f_w1.T + b1)
    mma_v3<0, 128, 128><<<dim3(2048, 2), 256, SMEM128>>>(x1, 256, f_w1, 256, 0, f_b1, x2, 256, 256, 1);
    // x3 = relu(x2 @ f_w2.T + b2) -> reuse b1
    mma_v3<0, 128, 128><<<dim3(2048, 2), 256, SMEM128>>>(x2, 256, f_w2, 256, 0, f_b2, b1, 256, 256, 1);
    // GI = x3 @ c_wih.T + c_bih
    mma_v3<0, 128, 128><<<dim3(2048, 6), 256, SMEM128>>>(b1, 256, c_wih, 256, 0, c_bih, gi, 768, 256, 0);

    // ---- sequential main loop: split3 tf32 gh (fp32-grade) + gates ----
    for (int t = 0; t < 256; t++) {
        const float* src = (t == 0) ? h0 : ((t & 1) ? hh0 : hh1);
        float* dst = (t & 1) ? hh1 : hh0;
        mma_v3<1, 64, 64><<<dim3(16, 12), 256, SMEM64>>>(src, 256, c_whh, 256, 0, nullptr,
                                                         ghm, 768, 256, 0);
        main_gate_kernel<<<256, 256>>>(src, ghm, gi, c_bhh, dst, out, t);
    }

    // ---- heads + packing (parallel over all T*N) ----
    head_kernel<<<8192, 256>>>(out, w_actor, b_actor, w_critic, b_critic,
                               actions, active, p0, pp0);
}

// round 8
// speedup vs baseline: 1.6840x; 1.6840x over previous
#include <cuda_runtime.h>
#include <cstdint>

#define OUTW 278   // 4 + 256 + 16 + 2
#define SMEM128 69632
// persistent main loop smem: W 8*96*34 + H 8*64*34 + GH 64*97 floats
#define PW  (8*96*34)
#define PH  (8*64*34)
#define PG  (64*97)
#define PSM ((PW + PH + PG) * 4)

// ---------------- scratch (device globals; no allocations allowed) ----------------
__device__ float S_MFLAT[16384 * 256];
__device__ float S_GF[16384 * 768];
__device__ float S_GB[16384 * 768];
__device__ float S_GH[16384 * 768];
__device__ float S_E0[16384 * 256];
__device__ float S_E1[16384 * 256];
__device__ float S_E2[16384 * 256];
__device__ float S_E3[16384 * 256];
__device__ float S_HCAT[16384 * 512];
__device__ float S_RP[16384 * 256];
__device__ float S_B1[262144 * 256];
__device__ float S_X1[262144 * 256];
__device__ float S_X2[262144 * 256];
__device__ float S_GI[(size_t)262144 * 768];
__device__ float S_H0[1024 * 256];
__device__ float S_H1[1024 * 256];
__device__ unsigned S_BARR[16];

__device__ __forceinline__ float sigm(float x) { return 1.0f / (1.0f + expf(-x)); }

__device__ __forceinline__ void spl(float x, unsigned& hi, unsigned& lo) {
    unsigned b = __float_as_uint(x);
    hi = b & 0xffffe000u;
    lo = __float_as_uint(x - __uint_as_float(hi));
}

__device__ __forceinline__ void mma8(float* c, const unsigned* a, const unsigned* b) {
    asm volatile(
        "mma.sync.aligned.m16n8k8.row.col.f32.tf32.tf32.f32 "
        "{%0,%1,%2,%3}, {%4,%5,%6,%7}, {%8,%9}, {%0,%1,%2,%3};"
        : "+f"(c[0]), "+f"(c[1]), "+f"(c[2]), "+f"(c[3])
        : "r"(a[0]), "r"(a[1]), "r"(a[2]), "r"(a[3]), "r"(b[0]), "r"(b[1]));
}

// ---------------- tf32 GEMM (batch ops): C = op(A @ W^T + bias) ----------------
template<int SPLIT3, int BMT, int BNT>
__global__ __launch_bounds__(256) void mma_v3(
    const float* __restrict__ A, int lda,
    const float* __restrict__ W, int ldw, int wcol0,
    const float* __restrict__ bias,
    float* __restrict__ C, int ldc, int K, int relu)
{
    constexpr int WTM = BMT / 4, WTN = BNT / 2;
    constexpr int MF  = WTM / 16, NF = WTN / 8;
    constexpr int AJ  = BMT / 32, BJ = BNT / 32;
    constexpr int SA  = BMT * 34, SB = BNT * 34;
    extern __shared__ float sm[];
    float* AsBase = sm;
    float* BsBase = sm + 2 * SA;

    const int tid  = threadIdx.x;
    const int lane = tid & 31, warp = tid >> 5;
    const int bm = blockIdx.x * BMT, bn = blockIdx.y * BNT;
    const int wm = (warp & 3) * WTM, wn = (warp >> 2) * WTN;
    const int lr = lane >> 2, lk = lane & 3;
    const int mld = tid >> 3, g = tid & 7;

    float acc[MF][NF][4] = {};
    const int KT = K / 32;
    float4 av[AJ], wv[BJ];

    {
        const float* Ab = A + (size_t)(bm + mld) * lda + g * 4;
        const float* Wb = W + (size_t)(bn + mld) * ldw + wcol0 + g * 4;
#pragma unroll
        for (int j = 0; j < AJ; j++) av[j] = *(const float4*)(Ab + (size_t)(32 * j) * lda);
#pragma unroll
        for (int j = 0; j < BJ; j++) wv[j] = *(const float4*)(Wb + (size_t)(32 * j) * ldw);
#pragma unroll
        for (int j = 0; j < AJ; j++) {
            float* p = AsBase + (mld + 32 * j) * 34 + g;
            p[0] = av[j].x; p[8] = av[j].y; p[16] = av[j].z; p[24] = av[j].w;
        }
#pragma unroll
        for (int j = 0; j < BJ; j++) {
            float* p = BsBase + (mld + 32 * j) * 34 + g;
            p[0] = wv[j].x; p[8] = wv[j].y; p[16] = wv[j].z; p[24] = wv[j].w;
        }
    }

    for (int kt = 0; kt < KT; kt++) {
        __syncthreads();
        const int buf = kt & 1;
        if (kt + 1 < KT) {
            int k0 = (kt + 1) * 32;
            const float* Ab = A + (size_t)(bm + mld) * lda + k0 + g * 4;
            const float* Wb = W + (size_t)(bn + mld) * ldw + wcol0 + k0 + g * 4;
#pragma unroll
            for (int j = 0; j < AJ; j++) av[j] = *(const float4*)(Ab + (size_t)(32 * j) * lda);
#pragma unroll
            for (int j = 0; j < BJ; j++) wv[j] = *(const float4*)(Wb + (size_t)(32 * j) * ldw);
        }

        const float* Ab = AsBase + buf * SA;
        const float* Bb = BsBase + buf * SB;
#pragma unroll
        for (int s = 0; s < 4; s++) {
            unsigned ah[MF][4], al[MF][4], bh[NF][2], bl[NF][2];
#pragma unroll
            for (int mf = 0; mf < MF; mf++) {
                int r0 = wm + mf * 16 + lr;
                float2 x0 = *(const float2*)(Ab + r0 * 34 + lk * 8 + 2 * s);
                float2 x1 = *(const float2*)(Ab + (r0 + 8) * 34 + lk * 8 + 2 * s);
                if (SPLIT3) {
                    spl(x0.x, ah[mf][0], al[mf][0]); spl(x1.x, ah[mf][1], al[mf][1]);
                    spl(x0.y, ah[mf][2], al[mf][2]); spl(x1.y, ah[mf][3], al[mf][3]);
                } else {
                    ah[mf][0] = __float_as_uint(x0.x); ah[mf][1] = __float_as_uint(x1.x);
                    ah[mf][2] = __float_as_uint(x0.y); ah[mf][3] = __float_as_uint(x1.y);
                }
            }
#pragma unroll
            for (int nf = 0; nf < NF; nf++) {
                int c0 = wn + nf * 8 + lr;
                float2 y = *(const float2*)(Bb + c0 * 34 + lk * 8 + 2 * s);
                if (SPLIT3) {
                    spl(y.x, bh[nf][0], bl[nf][0]); spl(y.y, bh[nf][1], bl[nf][1]);
                } else {
                    bh[nf][0] = __float_as_uint(y.x); bh[nf][1] = __float_as_uint(y.y);
                }
            }
#pragma unroll
            for (int mf = 0; mf < MF; mf++)
#pragma unroll
                for (int nf = 0; nf < NF; nf++) {
                    mma8(acc[mf][nf], ah[mf], bh[nf]);
                    if (SPLIT3) {
                        mma8(acc[mf][nf], ah[mf], bl[nf]);
                        mma8(acc[mf][nf], al[mf], bh[nf]);
                    }
                }
        }

        if (kt + 1 < KT) {
            float* Ad = AsBase + (buf ^ 1) * SA;
            float* Bd = BsBase + (buf ^ 1) * SB;
#pragma unroll
            for (int j = 0; j < AJ; j++) {
                float* p = Ad + (mld + 32 * j) * 34 + g;
                p[0] = av[j].x; p[8] = av[j].y; p[16] = av[j].z; p[24] = av[j].w;
            }
#pragma unroll
            for (int j = 0; j < BJ; j++) {
                float* p = Bd + (mld + 32 * j) * 34 + g;
                p[0] = wv[j].x; p[8] = wv[j].y; p[16] = wv[j].z; p[24] = wv[j].w;
            }
        }
    }

#pragma unroll
    for (int mf = 0; mf < MF; mf++) {
#pragma unroll
        for (int nf = 0; nf < NF; nf++) {
            int col = bn + wn + nf * 8 + lk * 2;
            float b0v = 0.f, b1v = 0.f;
            if (bias) { b0v = bias[col]; b1v = bias[col + 1]; }
            int r0 = bm + wm + mf * 16 + lr;
            float v0 = acc[mf][nf][0] + b0v, v1 = acc[mf][nf][1] + b1v;
            float v2 = acc[mf][nf][2] + b0v, v3 = acc[mf][nf][3] + b1v;
            if (relu) {
                v0 = fmaxf(v0, 0.f); v1 = fmaxf(v1, 0.f);
                v2 = fmaxf(v2, 0.f); v3 = fmaxf(v3, 0.f);
            }
            float2 p0; p0.x = v0; p0.y = v1;
            float2 p1; p1.x = v2; p1.y = v3;
            *reinterpret_cast<float2*>(&C[(size_t)r0 * ldc + col]) = p0;
            *reinterpret_cast<float2*>(&C[(size_t)(r0 + 8) * ldc + col]) = p1;
        }
    }
}

// ---------------- persistent fused main loop ----------------
// 128 CTAs: mg = cta>>3 (64 samples), cg = cta&7 (32 features/gate).
// Whh slice (96 rows x 256) resident in smem; split3 tf32 gh; fused gates.
__global__ __launch_bounds__(256) void main_loop_kernel(
    const float* __restrict__ h0, const float* __restrict__ Whh,
    const float* __restrict__ bhh, const float* __restrict__ GI,
    float* __restrict__ hb0, float* __restrict__ hb1, float* __restrict__ out)
{
    extern __shared__ float sm[];
    float* Wsm = sm;            // [8][96][34]
    float* Hsm = sm + PW;       // [8][64][34]
    float* GHs = sm + PW + PH;  // [64][97]
    const int tid = threadIdx.x, lane = tid & 31, warp = tid >> 5;
    const int mg = blockIdx.x >> 3, cg = blockIdx.x & 7;
    const int wm = (warp & 1) * 32, wn = (warp >> 1) * 24;
    const int lr = lane >> 2, lk = lane & 3;
    const int rr = tid >> 3, g8 = tid & 7;

    // load W slice once: smem row w (0..95) = gate(w/32)*256 + cg*32 + (w&31)
    for (int row = rr; row < 96; row += 32) {
        int grow = (row >> 5) * 256 + cg * 32 + (row & 31);
#pragma unroll
        for (int kc = 0; kc < 8; kc++) {
            float4 v = *(const float4*)(Whh + (size_t)grow * 256 + kc * 32 + g8 * 4);
            float* p = Wsm + kc * (96 * 34) + row * 34 + g8;
            p[0] = v.x; p[8] = v.y; p[16] = v.z; p[24] = v.w;
        }
    }

    // per-thread epilogue constants
    const int es = tid >> 2, eci = (tid & 3) * 8;   // sample in tile, col base
    float cbr[8], cbz[8], cbn[8];
#pragma unroll
    for (int i = 0; i < 8; i++) {
        int jj = cg * 32 + eci + i;
        cbr[i] = bhh[jj]; cbz[i] = bhh[256 + jj]; cbn[i] = bhh[512 + jj];
    }

    for (int t = 0; t < 256; t++) {
        // load h tile [64][256]
        const float* hsrc = (t == 0) ? (h0 + (size_t)mg * 64 * 256)
                                     : (((t & 1) ? hb1 : hb0) + (size_t)mg * 64 * 256);
        for (int row = rr; row < 64; row += 32) {
#pragma unroll
            for (int kc = 0; kc < 8; kc++) {
                float4 v = *(const float4*)(hsrc + (size_t)row * 256 + kc * 32 + g8 * 4);
                float* p = Hsm + kc * (64 * 34) + row * 34 + g8;
                p[0] = v.x; p[8] = v.y; p[16] = v.z; p[24] = v.w;
            }
        }
        __syncthreads();

        float acc[2][3][4] = {};
#pragma unroll 2
        for (int kc = 0; kc < 8; kc++) {
            const float* Hb = Hsm + kc * (64 * 34);
            const float* Wb = Wsm + kc * (96 * 34);
#pragma unroll
            for (int s = 0; s < 4; s++) {
                unsigned ah[2][4], al[2][4], bh[3][2], bl[3][2];
#pragma unroll
                for (int mf = 0; mf < 2; mf++) {
                    int r0 = wm + mf * 16 + lr;
                    float2 x0 = *(const float2*)(Hb + r0 * 34 + lk * 8 + 2 * s);
                    float2 x1 = *(const float2*)(Hb + (r0 + 8) * 34 + lk * 8 + 2 * s);
                    spl(x0.x, ah[mf][0], al[mf][0]); spl(x1.x, ah[mf][1], al[mf][1]);
                    spl(x0.y, ah[mf][2], al[mf][2]); spl(x1.y, ah[mf][3], al[mf][3]);
                }
#pragma unroll
                for (int nf = 0; nf < 3; nf++) {
                    int c0 = wn + nf * 8 + lr;
                    float2 y = *(const float2*)(Wb + c0 * 34 + lk * 8 + 2 * s);
                    spl(y.x, bh[nf][0], bl[nf][0]); spl(y.y, bh[nf][1], bl[nf][1]);
                }
#pragma unroll
                for (int mf = 0; mf < 2; mf++)
#pragma unroll
                    for (int nf = 0; nf < 3; nf++) {
                        mma8(acc[mf][nf], ah[mf], bh[nf]);
                        mma8(acc[mf][nf], ah[mf], bl[nf]);
                        mma8(acc[mf][nf], al[mf], bh[nf]);
                    }
            }
        }
        // stash gh tile to smem
#pragma unroll
        for (int mf = 0; mf < 2; mf++)
#pragma unroll
            for (int nf = 0; nf < 3; nf++) {
                int r0 = wm + mf * 16 + lr;
                int c = wn + nf * 8 + lk * 2;
                GHs[r0 * 97 + c] = acc[mf][nf][0];
                GHs[r0 * 97 + c + 1] = acc[mf][nf][1];
                GHs[(r0 + 8) * 97 + c] = acc[mf][nf][2];
                GHs[(r0 + 8) * 97 + c + 1] = acc[mf][nf][3];
            }
        __syncthreads();

        // fused gates: this thread -> sample es, cols cg*32+eci..+8
        {
            size_t grow = (size_t)t * 1024 + mg * 64 + es;
            const float* gi = GI + grow * 768 + cg * 32 + eci;
            const float* ghr = GHs + es * 97 + eci;
            float* hdst = ((t & 1) ? hb0 : hb1) + ((size_t)(mg * 64 + es)) * 256 + cg * 32 + eci;
            float* odst = out + grow * OUTW + 4 + cg * 32 + eci;
            float o[8];
#pragma unroll
            for (int i = 0; i < 8; i++) {
                int j = eci + i;
                int pk = (j & 3) * 8 + (j >> 2);
                float h = Hsm[cg * (64 * 34) + es * 34 + pk];
                float r = sigm(gi[i]       + ghr[i]      + cbr[i]);
                float z = sigm(gi[256 + i] + ghr[32 + i] + cbz[i]);
                float nn = tanhf(gi[512 + i] + r * (ghr[64 + i] + cbn[i]));
                o[i] = (1.f - z) * nn + z * h;
            }
#pragma unroll
            for (int q = 0; q < 8; q += 4) {
                float4 v; v.x = o[q]; v.y = o[q + 1]; v.z = o[q + 2]; v.w = o[q + 3];
                *(float4*)(hdst + q) = v;
            }
            // out row stride 278 ≡ 2 (mod 4): only 8B alignment guaranteed -> float2
#pragma unroll
            for (int q = 0; q < 8; q += 2) {
                float2 v; v.x = o[q]; v.y = o[q + 1];
                *(float2*)(odst + q) = v;
            }
        }
        __threadfence();
        __syncthreads();
        if (tid == 0) {
            atomicAdd(&S_BARR[mg], 1u);
            unsigned target = 8u * (unsigned)(t + 1);
            while (*(volatile unsigned*)&S_BARR[mg] < target) {}
        }
        __syncthreads();
        __threadfence();
    }
}

__global__ void reset_bar() { S_BARR[threadIdx.x] = 0; }

// ---------------- elementwise kernels ----------------
__global__ void enc_gate_kernel(const float* __restrict__ Hin,
                                const float* __restrict__ GH,
                                const float* __restrict__ GI,
                                const float* __restrict__ bhh,
                                float* __restrict__ Hout,
                                int loff, int hzero)
{
    int b = blockIdx.x * 4 + (threadIdx.x >> 6);
    int j = (threadIdx.x & 63) * 4;
    int n = b & 1023, roll = b >> 10;
    int l = (roll + loff) & 15;
    const float* gi = GI + ((size_t)n * 16 + l) * 768;
    float4 gr = *(const float4*)(gi + j);
    float4 gz = *(const float4*)(gi + 256 + j);
    float4 gn = *(const float4*)(gi + 512 + j);
    float4 hr = *(const float4*)(bhh + j);
    float4 hz = *(const float4*)(bhh + 256 + j);
    float4 hn = *(const float4*)(bhh + 512 + j);
    float4 h = make_float4(0.f, 0.f, 0.f, 0.f);
    if (!hzero) {
        const float* gh = GH + (size_t)b * 768;
        float4 tv;
        tv = *(const float4*)(gh + j);       hr.x += tv.x; hr.y += tv.y; hr.z += tv.z; hr.w += tv.w;
        tv = *(const float4*)(gh + 256 + j); hz.x += tv.x; hz.y += tv.y; hz.z += tv.z; hz.w += tv.w;
        tv = *(const float4*)(gh + 512 + j); hn.x += tv.x; hn.y += tv.y; hn.z += tv.z; hn.w += tv.w;
        h = *(const float4*)(Hin + (size_t)b * 256 + j);
    }
    float4 o;
    { float r = sigm(gr.x + hr.x), z = sigm(gz.x + hz.x);
      o.x = (1.f - z) * tanhf(gn.x + r * hn.x) + z * h.x; }
    { float r = sigm(gr.y + hr.y), z = sigm(gz.y + hz.y);
      o.y = (1.f - z) * tanhf(gn.y + r * hn.y) + z * h.y; }
    { float r = sigm(gr.z + hr.z), z = sigm(gz.z + hz.z);
      o.z = (1.f - z) * tanhf(gn.z + r * hn.z) + z * h.z; }
    { float r = sigm(gr.w + hr.w), z = sigm(gz.w + hz.w);
      o.w = (1.f - z) * tanhf(gn.w + r * hn.w) + z * h.w; }
    *(float4*)(Hout + (size_t)b * 256 + j) = o;
}

__global__ void gather_kernel(const int* __restrict__ lines,
                              const float* __restrict__ embed)
{
    int gid = blockIdx.x * 256 + threadIdx.x;
    int e = gid * 4;
    int row = e >> 8, j = e & 255;
    int line = lines[row];
    *(float4*)(S_MFLAT + (size_t)row * 256 + j) =
        *(const float4*)(embed + (size_t)line * 256 + j);
}

__global__ void hcat_kernel()
{
    int gid = blockIdx.x * 256 + threadIdx.x;
    int e = gid * 4;
    int row = e >> 9, c = e & 511;
    float4 v;
    if (c < 256) v = *(const float4*)(S_E0 + (size_t)row * 256 + c);
    else         v = *(const float4*)(S_E2 + (size_t)row * 256 + c - 256);
    *(float4*)(S_HCAT + (size_t)row * 512 + c) = v;
}

__global__ void x1_kernel(const int* __restrict__ active,
                          const float* __restrict__ b0)
{
    size_t gid = (size_t)blockIdx.x * 256 + threadIdx.x;
    size_t e = gid * 4;
    size_t row = e >> 8;
    int j = (int)(e & 255);
    int n = (int)(row & 1023);
    int w = active[row];
    float4 a = *(const float4*)(S_B1 + row * 256 + j);
    float4 r = *(const float4*)(S_RP + ((size_t)w * 1024 + n) * 256 + j);
    float4 b = *(const float4*)(b0 + j);
    float4 o;
    o.x = fmaxf(a.x + r.x + b.x, 0.f);
    o.y = fmaxf(a.y + r.y + b.y, 0.f);
    o.z = fmaxf(a.z + r.z + b.z, 0.f);
    o.w = fmaxf(a.w + r.w + b.w, 0.f);
    *(float4*)(S_X1 + row * 256 + j) = o;
}

__global__ __launch_bounds__(256) void head_kernel(
    float* __restrict__ out,
    const float* __restrict__ w_actor, const float* __restrict__ b_actor,
    const float* __restrict__ w_critic, const float* __restrict__ b_critic,
    const int* __restrict__ actions, const int* __restrict__ active,
    const float* __restrict__ p0, const float* __restrict__ pp0)
{
    __shared__ float wa[16][257];
    __shared__ float wc[256];
    int tid = threadIdx.x;
    for (int idx = tid; idx < 16 * 256; idx += 256)
        wa[idx >> 8][idx & 255] = w_actor[idx];
    wc[tid] = w_critic[tid];
    __syncthreads();

    int warp = tid >> 5, lane = tid & 31;
#pragma unroll 1
    for (int rr = 0; rr < 4; rr++) {
        size_t row = (size_t)blockIdx.x * 32 + warp * 4 + rr;
        float* orow = out + row * OUTW;
        const float* hrow = orow + 4;
        const float* wrow = (lane < 16) ? wa[lane] : wc;
        float acc = 0.0f;
#pragma unroll 8
        for (int j = 0; j < 256; j++) acc += hrow[j] * wrow[j];
        if (lane < 16) acc += b_actor[lane];
        else if (lane == 16) acc += b_critic[0];

        float lg = (lane < 16) ? acc : -1e30f;
        float m = lg;
#pragma unroll
        for (int o = 8; o > 0; o >>= 1)
            m = fmaxf(m, __shfl_xor_sync(0xffffffffu, m, o, 16));
        float e = expf(lg - m);
        float s = e;
#pragma unroll
        for (int o = 8; o > 0; o >>= 1)
            s += __shfl_xor_sync(0xffffffffu, s, o, 16);
        float p = e / s;

        int n = (int)(row & 1023);
        if (lane < 16)       orow[260 + lane] = p;
        else if (lane == 16) orow[3]   = acc;
        else if (lane == 17) orow[0]   = (float)actions[row];
        else if (lane == 18) orow[1]   = p0[n];
        else if (lane == 19) orow[2]   = (float)active[row];
        else if (lane == 20) orow[276] = pp0[2 * n];
        else if (lane == 21) orow[277] = pp0[2 * n + 1];
    }
}

// ---------------- launcher ----------------
extern "C" void kernel_launch(void* const* d_in, const int* in_sizes, int n_in,
                              void* d_out, int out_size)
{
    const float* condition = (const float*)d_in[0];
    const int*   active    = (const int*)d_in[1];
    const int*   lines     = (const int*)d_in[2];
    const int*   actions   = (const int*)d_in[3];
    const float* h0        = (const float*)d_in[4];
    const float* p0        = (const float*)d_in[5];
    const float* pp0       = (const float*)d_in[6];
    const float* embed     = (const float*)d_in[7];
    const float* wih_f     = (const float*)d_in[8];
    const float* whh_f     = (const float*)d_in[9];
    const float* bih_f     = (const float*)d_in[10];
    const float* bhh_f     = (const float*)d_in[11];
    const float* wih_b     = (const float*)d_in[12];
    const float* whh_b     = (const float*)d_in[13];
    const float* bih_b     = (const float*)d_in[14];
    const float* bhh_b     = (const float*)d_in[15];
    const float* f_w0      = (const float*)d_in[16];
    const float* f_b0      = (const float*)d_in[17];
    const float* f_w1      = (const float*)d_in[18];
    const float* f_b1      = (const float*)d_in[19];
    const float* f_w2      = (const float*)d_in[20];
    const float* f_b2      = (const float*)d_in[21];
    const float* c_wih     = (const float*)d_in[22];
    const float* c_whh     = (const float*)d_in[23];
    const float* c_bih     = (const float*)d_in[24];
    const float* c_bhh     = (const float*)d_in[25];
    const float* w_critic  = (const float*)d_in[26];
    const float* b_critic  = (const float*)d_in[27];
    const float* w_actor   = (const float*)d_in[28];
    const float* b_actor   = (const float*)d_in[29];
    float* out = (float*)d_out;

    float *mflat, *gf, *gb, *gh, *e0, *e1, *e2, *e3, *hcat, *rp, *b1, *x1, *x2, *gi, *hh0, *hh1;
    cudaGetSymbolAddress((void**)&mflat, S_MFLAT);
    cudaGetSymbolAddress((void**)&gf,    S_GF);
    cudaGetSymbolAddress((void**)&gb,    S_GB);
    cudaGetSymbolAddress((void**)&gh,    S_GH);
    cudaGetSymbolAddress((void**)&e0,    S_E0);
    cudaGetSymbolAddress((void**)&e1,    S_E1);
    cudaGetSymbolAddress((void**)&e2,    S_E2);
    cudaGetSymbolAddress((void**)&e3,    S_E3);
    cudaGetSymbolAddress((void**)&hcat,  S_HCAT);
    cudaGetSymbolAddress((void**)&rp,    S_RP);
    cudaGetSymbolAddress((void**)&b1,    S_B1);
    cudaGetSymbolAddress((void**)&x1,    S_X1);
    cudaGetSymbolAddress((void**)&x2,    S_X2);
    cudaGetSymbolAddress((void**)&gi,    S_GI);
    cudaGetSymbolAddress((void**)&hh0,   S_H0);
    cudaGetSymbolAddress((void**)&hh1,   S_H1);

    cudaFuncSetAttribute(mma_v3<0, 128, 128>, cudaFuncAttributeMaxDynamicSharedMemorySize, SMEM128);
    cudaFuncSetAttribute(main_loop_kernel, cudaFuncAttributeMaxDynamicSharedMemorySize, PSM);

    // ---- task encoder ----
    gather_kernel<<<4096, 256>>>(lines, embed);
    mma_v3<0, 128, 128><<<dim3(128, 6), 256, SMEM128>>>(mflat, 256, wih_f, 256, 0, bih_f, gf, 768, 256, 0);
    mma_v3<0, 128, 128><<<dim3(128, 6), 256, SMEM128>>>(mflat, 256, wih_b, 256, 0, bih_b, gb, 768, 256, 0);

    for (int t = 0; t < 16; t++) {
        const float* src = (t & 1) ? e1 : e0;
        float* dst = (t & 1) ? e0 : e1;
        if (t > 0)
            mma_v3<0, 128, 128><<<dim3(128, 6), 256, SMEM128>>>(src, 256, whh_f, 256, 0, nullptr,
                                                                gh, 768, 256, 0);
        enc_gate_kernel<<<4096, 256>>>(src, gh, gf, bhh_f, dst, t, t == 0);
    }
    for (int s = 0; s < 16; s++) {
        const float* src = (s & 1) ? e3 : e2;
        float* dst = (s & 1) ? e2 : e3;
        if (s > 0)
            mma_v3<0, 128, 128><<<dim3(128, 6), 256, SMEM128>>>(src, 256, whh_b, 256, 0, nullptr,
                                                                gh, 768, 256, 0);
        enc_gate_kernel<<<4096, 256>>>(src, gh, gb, bhh_b, dst, 15 - s, s == 0);
    }
    hcat_kernel<<<8192, 256>>>();

    // ---- main-loop parallel precompute ----
    mma_v3<0, 128, 128><<<dim3(128, 2), 256, SMEM128>>>(hcat, 512, f_w0, 576, 64, nullptr, rp, 256, 512, 0);
    mma_v3<0, 128, 128><<<dim3(2048, 2), 256, SMEM128>>>(condition, 64, f_w0, 576, 0, nullptr, b1, 256, 64, 0);
    x1_kernel<<<65536, 256>>>(active, f_b0);
    mma_v3<0, 128, 128><<<dim3(2048, 2), 256, SMEM128>>>(x1, 256, f_w1, 256, 0, f_b1, x2, 256, 256, 1);
    mma_v3<0, 128, 128><<<dim3(2048, 2), 256, SMEM128>>>(x2, 256, f_w2, 256, 0, f_b2, b1, 256, 256, 1);
    mma_v3<0, 128, 128><<<dim3(2048, 6), 256, SMEM128>>>(b1, 256, c_wih, 256, 0, c_bih, gi, 768, 256, 0);

    // ---- persistent fused sequential main loop ----
    reset_bar<<<1, 16>>>();
    main_loop_kernel<<<128, 256, PSM>>>(h0, c_whh, c_bhh, gi, hh0, hh1, out);

    // ---- heads + packing ----
    head_kernel<<<8192, 256>>>(out, w_actor, b_actor, w_critic, b_critic,
                               actions, active, p0, pp0);
}